// round 14
// baseline (speedup 1.0000x reference)
#include <cuda_runtime.h>
#include <cuda_fp16.h>
#include <math.h>
#include <cstdint>
#include <cstddef>

#define NN       50000
#define EE       800000
#define ETOT     (EE + NN)
#define FDIM     128

// ---------------- scratch ----------------
__device__ __half g_h[(size_t)NN * FDIM];
__device__ float  g_bufB[(size_t)NN * FDIM];
__device__ float  g_es[NN * 2];
__device__ float  g_ed[NN * 2];
__device__ int    g_rowptr[NN + 1];
__device__ int    g_wp[NN];
__device__ int    g_col[ETOT];

// ---------------- CSR build ----------------
__global__ void zero_counts_kernel(int n) {
    int i = blockIdx.x * blockDim.x + threadIdx.x;
    if (i < n) g_wp[i] = 0;
}

__global__ void hist_kernel(const int* __restrict__ ei, int E, int n) {
    int e = blockIdx.x * blockDim.x + threadIdx.x;
    int etot = E + n;
    if (e >= etot) return;
    int d = (e < E) ? ei[E + e] : (e - E);
    atomicAdd(&g_wp[d], 1);
}

__global__ __launch_bounds__(1024) void scan_kernel(int n) {
    __shared__ int wsum[32];
    __shared__ int carry_sh;
    int lane = threadIdx.x & 31, wid = threadIdx.x >> 5;
    if (threadIdx.x == 0) carry_sh = 0;
    __syncthreads();
    for (int base = 0; base < n; base += 4096) {
        int idx = base + threadIdx.x * 4;
        int v0 = (idx + 0 < n) ? g_wp[idx + 0] : 0;
        int v1 = (idx + 1 < n) ? g_wp[idx + 1] : 0;
        int v2 = (idx + 2 < n) ? g_wp[idx + 2] : 0;
        int v3 = (idx + 3 < n) ? g_wp[idx + 3] : 0;
        int tsum = v0 + v1 + v2 + v3;
        int x = tsum;
#pragma unroll
        for (int off = 1; off < 32; off <<= 1) {
            int y = __shfl_up_sync(0xffffffffu, x, off);
            if (lane >= off) x += y;
        }
        if (lane == 31) wsum[wid] = x;
        __syncthreads();
        if (wid == 0) {
            int ws = wsum[lane];
#pragma unroll
            for (int off = 1; off < 32; off <<= 1) {
                int y = __shfl_up_sync(0xffffffffu, ws, off);
                if (lane >= off) ws += y;
            }
            wsum[lane] = ws;
        }
        __syncthreads();
        int carry = carry_sh;
        int excl = carry + (wid ? wsum[wid - 1] : 0) + (x - tsum);
        if (idx + 0 < n) { g_rowptr[idx + 0] = excl; g_wp[idx + 0] = excl; } excl += v0;
        if (idx + 1 < n) { g_rowptr[idx + 1] = excl; g_wp[idx + 1] = excl; } excl += v1;
        if (idx + 2 < n) { g_rowptr[idx + 2] = excl; g_wp[idx + 2] = excl; } excl += v2;
        if (idx + 3 < n) { g_rowptr[idx + 3] = excl; g_wp[idx + 3] = excl; }
        int total = wsum[31];
        __syncthreads();
        if (threadIdx.x == 0) carry_sh = carry + total;
        __syncthreads();
    }
    if (threadIdx.x == 0) g_rowptr[n] = carry_sh;
}

__global__ void scatter_kernel(const int* __restrict__ ei, int E, int n) {
    int e = blockIdx.x * blockDim.x + threadIdx.x;
    int etot = E + n;
    if (e >= etot) return;
    int s, d;
    if (e < E) { s = ei[e]; d = ei[E + e]; }
    else       { s = e - E; d = s; }
    int p = atomicAdd(&g_wp[d], 1);
    g_col[p] = s;
}

// ---------------- tf32 helpers ----------------
__device__ __forceinline__ uint32_t f2tf32(float x) {
    uint32_t r;
    asm("cvt.rna.tf32.f32 %0, %1;" : "=r"(r) : "f"(x));
    return r;
}
__device__ __forceinline__ void mma_tf32(float* c, const uint32_t* a, const uint32_t* b) {
    asm volatile(
        "mma.sync.aligned.m16n8k8.row.col.f32.tf32.tf32.f32 "
        "{%0,%1,%2,%3},{%4,%5,%6,%7},{%8,%9},{%0,%1,%2,%3};"
        : "+f"(c[0]), "+f"(c[1]), "+f"(c[2]), "+f"(c[3])
        : "r"(a[0]), "r"(a[1]), "r"(a[2]), "r"(a[3]), "r"(b[0]), "r"(b[1]));
}

// ---------------- 3xTF32 GEMM: B hi/lo precomputed in smem ----------------
// Dynamic smem: As f32[128][36] | Bh u32[32][136] | Bl u32[32][136]  (53248 B)
#define SMEM_AS_BYTES   (128 * 36 * 4)
#define SMEM_B_BYTES    (32 * 136 * 4)
#define SGEMM_SMEM      (SMEM_AS_BYTES + 2 * SMEM_B_BYTES)

__global__ __launch_bounds__(256, 2) void sgemm128_kernel(
    const float* __restrict__ A, const float* __restrict__ W,
    const float* __restrict__ av_src, const float* __restrict__ av_dst,
    __half* __restrict__ Ch, int M)
{
    extern __shared__ char dynsmem[];
    float    (*As)[36]  = reinterpret_cast<float(*)[36]>(dynsmem);
    uint32_t (*Bh)[136] = reinterpret_cast<uint32_t(*)[136]>(dynsmem + SMEM_AS_BYTES);
    uint32_t (*Bl)[136] = reinterpret_cast<uint32_t(*)[136]>(dynsmem + SMEM_AS_BYTES + SMEM_B_BYTES);

    int block_row = blockIdx.x * 128;
    int tid  = threadIdx.x;
    int lane = tid & 31;
    int warp = tid >> 5;
    int wr = warp >> 1;
    int wc = warp & 1;              // == attention head
    int lq = lane >> 2;
    int lr = lane & 3;

    float c[2][8][4];
#pragma unroll
    for (int mt = 0; mt < 2; mt++)
#pragma unroll
        for (int nt = 0; nt < 8; nt++)
#pragma unroll
            for (int i = 0; i < 4; i++) c[mt][nt][i] = 0.f;

    for (int kc = 0; kc < 4; kc++) {
        int k0 = kc * 32;
#pragma unroll
        for (int i = 0; i < 4; i++) {
            int idx = tid + i * 256;
            int ar = idx >> 3, ac4 = (idx & 7) * 4;
            int gr = block_row + ar;
            float4 v = make_float4(0.f, 0.f, 0.f, 0.f);
            if (gr < M) v = *reinterpret_cast<const float4*>(&A[(size_t)gr * 128 + k0 + ac4]);
            *reinterpret_cast<float4*>(&As[ar][ac4]) = v;
            // B: convert to tf32 hi/lo once, cooperatively
            int br = idx >> 5, bc4 = (idx & 31) * 4;
            float4 wv = *reinterpret_cast<const float4*>(&W[(size_t)(k0 + br) * 128 + bc4]);
            uint32_t h0 = f2tf32(wv.x), h1 = f2tf32(wv.y), h2 = f2tf32(wv.z), h3 = f2tf32(wv.w);
            uint32_t l0 = f2tf32(wv.x - __uint_as_float(h0));
            uint32_t l1 = f2tf32(wv.y - __uint_as_float(h1));
            uint32_t l2 = f2tf32(wv.z - __uint_as_float(h2));
            uint32_t l3 = f2tf32(wv.w - __uint_as_float(h3));
            *reinterpret_cast<uint4*>(&Bh[br][bc4]) = make_uint4(h0, h1, h2, h3);
            *reinterpret_cast<uint4*>(&Bl[br][bc4]) = make_uint4(l0, l1, l2, l3);
        }
        __syncthreads();
#pragma unroll
        for (int ks = 0; ks < 4; ks++) {
            int k = ks * 8;
            uint32_t ah[2][4], al[2][4];
#pragma unroll
            for (int mt = 0; mt < 2; mt++) {
                int r0 = wr * 32 + mt * 16 + lq;
                float x0 = As[r0][k + lr];
                float x1 = As[r0 + 8][k + lr];
                float x2 = As[r0][k + lr + 4];
                float x3 = As[r0 + 8][k + lr + 4];
                ah[mt][0] = f2tf32(x0); al[mt][0] = f2tf32(x0 - __uint_as_float(ah[mt][0]));
                ah[mt][1] = f2tf32(x1); al[mt][1] = f2tf32(x1 - __uint_as_float(ah[mt][1]));
                ah[mt][2] = f2tf32(x2); al[mt][2] = f2tf32(x2 - __uint_as_float(ah[mt][2]));
                ah[mt][3] = f2tf32(x3); al[mt][3] = f2tf32(x3 - __uint_as_float(ah[mt][3]));
            }
#pragma unroll
            for (int nt = 0; nt < 8; nt++) {
                int ncol = wc * 64 + nt * 8 + lq;
                uint32_t bh[2], bl[2];
                bh[0] = Bh[k + lr][ncol];
                bh[1] = Bh[k + lr + 4][ncol];
                bl[0] = Bl[k + lr][ncol];
                bl[1] = Bl[k + lr + 4][ncol];
#pragma unroll
                for (int mt = 0; mt < 2; mt++) {
                    mma_tf32(c[mt][nt], ah[mt], bh);
                    mma_tf32(c[mt][nt], ah[mt], bl);
                    mma_tf32(c[mt][nt], al[mt], bh);
                }
            }
        }
        __syncthreads();
    }

    // store C as fp16
#pragma unroll
    for (int mt = 0; mt < 2; mt++) {
        int r0 = block_row + wr * 32 + mt * 16 + lq;
#pragma unroll
        for (int nt = 0; nt < 8; nt++) {
            int cc = wc * 64 + nt * 8 + lr * 2;
            if (r0 < M)
                *reinterpret_cast<__half2*>(&Ch[(size_t)r0 * 128 + cc]) =
                    __floats2half2_rn(c[mt][nt][0], c[mt][nt][1]);
            if (r0 + 8 < M)
                *reinterpret_cast<__half2*>(&Ch[(size_t)(r0 + 8) * 128 + cc]) =
                    __floats2half2_rn(c[mt][nt][2], c[mt][nt][3]);
        }
    }

    // fused e_src / e_dst epilogue from fp32 accumulators
#pragma unroll
    for (int mt = 0; mt < 2; mt++) {
#pragma unroll
        for (int half = 0; half < 2; half++) {
            float ps = 0.f, pd = 0.f;
#pragma unroll
            for (int nt = 0; nt < 8; nt++) {
                int cc = wc * 64 + nt * 8 + lr * 2;
                float v0 = c[mt][nt][half * 2 + 0];
                float v1 = c[mt][nt][half * 2 + 1];
                ps += v0 * av_src[cc] + v1 * av_src[cc + 1];
                pd += v0 * av_dst[cc] + v1 * av_dst[cc + 1];
            }
            ps += __shfl_xor_sync(0xffffffffu, ps, 1);
            pd += __shfl_xor_sync(0xffffffffu, pd, 1);
            ps += __shfl_xor_sync(0xffffffffu, ps, 2);
            pd += __shfl_xor_sync(0xffffffffu, pd, 2);
            int row = block_row + wr * 32 + mt * 16 + lq + half * 8;
            if (lr == 0 && row < M) {
                g_es[2 * row + wc] = ps;
                g_ed[2 * row + wc] = pd;
            }
        }
    }
}

__device__ __forceinline__ float lrelu(float x) { return x > 0.f ? x : 0.2f * x; }

// ---------------- fused softmax-aggregate: warp per (node, head) ----------------
// Each warp handles one head's 64 cols (128B half-row). 8 lanes per edge ->
// 4 edges per gather step. Merge subsets via shfl_xor(8) and shfl_xor(16).
__global__ __launch_bounds__(256) void agg_kernel(
    const __half* __restrict__ h, const float* __restrict__ bias,
    float* __restrict__ out, int n)
{
    int gw = (blockIdx.x * blockDim.x + threadIdx.x) >> 5;
    int lane = threadIdx.x & 31;
    if (gw >= 2 * n) return;
    int node = gw >> 1;
    int head = gw & 1;

    int start = g_rowptr[node], end = g_rowptr[node + 1];
    int deg = end - start;
    float edv = g_ed[2 * node + head];
    const uint4* h16 = reinterpret_cast<const uint4*>(h);  // 16 uint4 per 256B row
    int l7   = lane & 7;     // col group within head (8B each)
    int quad = lane >> 3;    // 0..3: edge offset within step

    float acc[8];
#pragma unroll
    for (int j = 0; j < 8; j++) acc[j] = 0.f;
    float den = 0.f;

    if (deg <= 32) {
        // fast path: metadata loaded once, logits in regs
        int s = 0; float l0 = -3.0e38f;
        if (lane < deg) {
            s = g_col[start + lane];
            l0 = lrelu(g_es[2 * s + head] + edv);
        }
        float m0 = l0;
#pragma unroll
        for (int o = 16; o; o >>= 1)
            m0 = fmaxf(m0, __shfl_xor_sync(0xffffffffu, m0, o));
        float w0 = (lane < deg) ? __expf(l0 - m0) : 0.f;
        den = w0;
#pragma unroll 2
        for (int k4 = 0; k4 < deg; k4 += 4) {
            int e = k4 + quad;
            int   ss = __shfl_sync(0xffffffffu, s,  e & 31);
            float wk = __shfl_sync(0xffffffffu, w0, e & 31);
            if (e >= deg) wk = 0.f;
            uint4 u = h16[(size_t)ss * 16 + head * 8 + l7];
            float2 f0 = __half22float2(*reinterpret_cast<const __half2*>(&u.x));
            float2 f1 = __half22float2(*reinterpret_cast<const __half2*>(&u.y));
            float2 f2 = __half22float2(*reinterpret_cast<const __half2*>(&u.z));
            float2 f3 = __half22float2(*reinterpret_cast<const __half2*>(&u.w));
            acc[0] += wk * f0.x; acc[1] += wk * f0.y;
            acc[2] += wk * f1.x; acc[3] += wk * f1.y;
            acc[4] += wk * f2.x; acc[5] += wk * f2.y;
            acc[6] += wk * f3.x; acc[7] += wk * f3.y;
        }
    } else {
        // general path
        float m0 = -3.0e38f;
        for (int j = start + lane; j < end; j += 32) {
            int s = g_col[j];
            m0 = fmaxf(m0, lrelu(g_es[2 * s + head] + edv));
        }
#pragma unroll
        for (int o = 16; o; o >>= 1)
            m0 = fmaxf(m0, __shfl_xor_sync(0xffffffffu, m0, o));
        for (int chunk = start; chunk < end; chunk += 32) {
            int j = chunk + lane;
            int s = 0; float w0 = 0.f;
            if (j < end) {
                s = g_col[j];
                w0 = __expf(lrelu(g_es[2 * s + head] + edv) - m0);
            }
            den += w0;
            int cnt = min(32, end - chunk);
#pragma unroll 2
            for (int k4 = 0; k4 < cnt; k4 += 4) {
                int e = k4 + quad;
                int   ss = __shfl_sync(0xffffffffu, s,  e & 31);
                float wk = __shfl_sync(0xffffffffu, w0, e & 31);
                if (e >= cnt) wk = 0.f;
                uint4 u = h16[(size_t)ss * 16 + head * 8 + l7];
                float2 f0 = __half22float2(*reinterpret_cast<const __half2*>(&u.x));
                float2 f1 = __half22float2(*reinterpret_cast<const __half2*>(&u.y));
                float2 f2 = __half22float2(*reinterpret_cast<const __half2*>(&u.z));
                float2 f3 = __half22float2(*reinterpret_cast<const __half2*>(&u.w));
                acc[0] += wk * f0.x; acc[1] += wk * f0.y;
                acc[2] += wk * f1.x; acc[3] += wk * f1.y;
                acc[4] += wk * f2.x; acc[5] += wk * f2.y;
                acc[6] += wk * f3.x; acc[7] += wk * f3.y;
            }
        }
    }

    // merge the 4 edge-subsets (lanes l, l+8, l+16, l+24 cover same cols)
#pragma unroll
    for (int j = 0; j < 8; j++) {
        acc[j] += __shfl_xor_sync(0xffffffffu, acc[j], 8);
        acc[j] += __shfl_xor_sync(0xffffffffu, acc[j], 16);
    }
#pragma unroll
    for (int o = 16; o; o >>= 1)
        den += __shfl_xor_sync(0xffffffffu, den, o);
    float inv = 1.0f / den;

    // output: lanes 0-15 write the head's 64 floats (16 float4)
    if (lane < 16) {
        int half16 = lane >> 3;                 // 0: acc[0..3], 1: acc[4..7]
        int fi = head * 16 + 2 * l7 + half16;   // float4 index within row
        const float* a = acc + half16 * 4;
        float4 bb = reinterpret_cast<const float4*>(bias)[fi];
        float o0 = a[0] * inv + bb.x;
        float o1 = a[1] * inv + bb.y;
        float o2 = a[2] * inv + bb.z;
        float o3 = a[3] * inv + bb.w;
        o0 = o0 > 0.f ? o0 : expm1f(o0);
        o1 = o1 > 0.f ? o1 : expm1f(o1);
        o2 = o2 > 0.f ? o2 : expm1f(o2);
        o3 = o3 > 0.f ? o3 : expm1f(o3);
        reinterpret_cast<float4*>(out)[(size_t)node * 32 + fi] =
            make_float4(o0, o1, o2, o3);
    }
}

// ---------------- host ----------------
extern "C" void kernel_launch(void* const* d_in, const int* in_sizes, int n_in,
                              void* d_out, int out_size)
{
    const float* x   = (const float*)d_in[0];
    const int*   ei  = (const int*)d_in[1];
    const float* W1  = (const float*)d_in[2];
    const float* as1 = (const float*)d_in[3];
    const float* ad1 = (const float*)d_in[4];
    const float* b1  = (const float*)d_in[5];
    const float* W2  = (const float*)d_in[6];
    const float* as2 = (const float*)d_in[7];
    const float* ad2 = (const float*)d_in[8];
    const float* b2  = (const float*)d_in[9];
    const float* W3  = (const float*)d_in[10];
    const float* as3 = (const float*)d_in[11];
    const float* ad3 = (const float*)d_in[12];
    const float* b3  = (const float*)d_in[13];
    float*       out = (float*)d_out;

    int n = in_sizes[0] / FDIM;          // 50000
    int E = in_sizes[1] / 2;             // 800000

    void* pH; cudaGetSymbolAddress(&pH, g_h);
    void* pB; cudaGetSymbolAddress(&pB, g_bufB);
    __half* hbuf = (__half*)pH;
    float*  bufB = (float*)pB;

    static int smem_set = 0;
    if (!smem_set) {
        cudaFuncSetAttribute(sgemm128_kernel,
                             cudaFuncAttributeMaxDynamicSharedMemorySize, SGEMM_SMEM);
        smem_set = 1;
    }

    int nblkNodes = (n + 255) / 256;
    int nblkEdges = (E + n + 255) / 256;
    int nblkWarp2 = (2 * n * 32 + 255) / 256;
    int nblkGemm  = (n + 127) / 128;

    // launches 0..2: CSR front half
    zero_counts_kernel<<<nblkNodes, 256>>>(n);
    hist_kernel<<<nblkEdges, 256>>>(ei, E, n);
    scan_kernel<<<1, 1024>>>(n);
    // launch 3: sgemm1 (ncu capture offset)
    sgemm128_kernel<<<nblkGemm, 256, SGEMM_SMEM>>>(x, W1, as1, ad1, hbuf, n);
    // launch 4: scatter completes CSR before agg1
    scatter_kernel<<<nblkEdges, 256>>>(ei, E, n);
    // launch 5: agg1
    agg_kernel<<<nblkWarp2, 256>>>(hbuf, b1, bufB, n);
    // layer 2
    sgemm128_kernel<<<nblkGemm, 256, SGEMM_SMEM>>>(bufB, W2, as2, ad2, hbuf, n);
    agg_kernel<<<nblkWarp2, 256>>>(hbuf, b2, bufB, n);
    // layer 3
    sgemm128_kernel<<<nblkGemm, 256, SGEMM_SMEM>>>(bufB, W3, as3, ad3, hbuf, n);
    agg_kernel<<<nblkWarp2, 256>>>(hbuf, b3, out, n);
}

// round 17
// speedup vs baseline: 1.1523x; 1.1523x over previous
#include <cuda_runtime.h>
#include <cuda_fp16.h>
#include <math.h>
#include <cstdint>
#include <cstddef>

#define NN       50000
#define EE       800000
#define ETOT     (EE + NN)
#define FDIM     128

// ---------------- scratch ----------------
__device__ __half g_h[(size_t)NN * FDIM];
__device__ float  g_bufB[(size_t)NN * FDIM];
__device__ float  g_es[NN * 2];
__device__ float  g_ed[NN * 2];
__device__ int    g_rowptr[NN + 1];
__device__ int    g_wp[NN];
__device__ int    g_col[ETOT];

// ---------------- CSR build ----------------
__global__ void zero_counts_kernel(int n) {
    int i = blockIdx.x * blockDim.x + threadIdx.x;
    if (i < n) g_wp[i] = 0;
}

__global__ void hist_kernel(const int* __restrict__ ei, int E, int n) {
    int e = blockIdx.x * blockDim.x + threadIdx.x;
    int etot = E + n;
    if (e >= etot) return;
    int d = (e < E) ? ei[E + e] : (e - E);
    atomicAdd(&g_wp[d], 1);
}

__global__ __launch_bounds__(1024) void scan_kernel(int n) {
    __shared__ int wsum[32];
    __shared__ int carry_sh;
    int lane = threadIdx.x & 31, wid = threadIdx.x >> 5;
    if (threadIdx.x == 0) carry_sh = 0;
    __syncthreads();
    for (int base = 0; base < n; base += 4096) {
        int idx = base + threadIdx.x * 4;
        int v0 = (idx + 0 < n) ? g_wp[idx + 0] : 0;
        int v1 = (idx + 1 < n) ? g_wp[idx + 1] : 0;
        int v2 = (idx + 2 < n) ? g_wp[idx + 2] : 0;
        int v3 = (idx + 3 < n) ? g_wp[idx + 3] : 0;
        int tsum = v0 + v1 + v2 + v3;
        int x = tsum;
#pragma unroll
        for (int off = 1; off < 32; off <<= 1) {
            int y = __shfl_up_sync(0xffffffffu, x, off);
            if (lane >= off) x += y;
        }
        if (lane == 31) wsum[wid] = x;
        __syncthreads();
        if (wid == 0) {
            int ws = wsum[lane];
#pragma unroll
            for (int off = 1; off < 32; off <<= 1) {
                int y = __shfl_up_sync(0xffffffffu, ws, off);
                if (lane >= off) ws += y;
            }
            wsum[lane] = ws;
        }
        __syncthreads();
        int carry = carry_sh;
        int excl = carry + (wid ? wsum[wid - 1] : 0) + (x - tsum);
        if (idx + 0 < n) { g_rowptr[idx + 0] = excl; g_wp[idx + 0] = excl; } excl += v0;
        if (idx + 1 < n) { g_rowptr[idx + 1] = excl; g_wp[idx + 1] = excl; } excl += v1;
        if (idx + 2 < n) { g_rowptr[idx + 2] = excl; g_wp[idx + 2] = excl; } excl += v2;
        if (idx + 3 < n) { g_rowptr[idx + 3] = excl; g_wp[idx + 3] = excl; }
        int total = wsum[31];
        __syncthreads();
        if (threadIdx.x == 0) carry_sh = carry + total;
        __syncthreads();
    }
    if (threadIdx.x == 0) g_rowptr[n] = carry_sh;
}

__global__ void scatter_kernel(const int* __restrict__ ei, int E, int n) {
    int e = blockIdx.x * blockDim.x + threadIdx.x;
    int etot = E + n;
    if (e >= etot) return;
    int s, d;
    if (e < E) { s = ei[e]; d = ei[E + e]; }
    else       { s = e - E; d = s; }
    int p = atomicAdd(&g_wp[d], 1);
    g_col[p] = s;
}

// ---------------- tf32 helpers ----------------
__device__ __forceinline__ uint32_t f2tf32(float x) {
    uint32_t r;
    asm("cvt.rna.tf32.f32 %0, %1;" : "=r"(r) : "f"(x));
    return r;
}
__device__ __forceinline__ void mma_tf32(float* c, const uint32_t* a, const uint32_t* b) {
    asm volatile(
        "mma.sync.aligned.m16n8k8.row.col.f32.tf32.tf32.f32 "
        "{%0,%1,%2,%3},{%4,%5,%6,%7},{%8,%9},{%0,%1,%2,%3};"
        : "+f"(c[0]), "+f"(c[1]), "+f"(c[2]), "+f"(c[3])
        : "r"(a[0]), "r"(a[1]), "r"(a[2]), "r"(a[3]), "r"(b[0]), "r"(b[1]));
}

// ---------------- 3xTF32 GEMM: B hi/lo precomputed in smem ----------------
// Dynamic smem: As f32[128][36] | Bh u32[32][136] | Bl u32[32][136]  (53248 B)
#define SMEM_AS_BYTES   (128 * 36 * 4)
#define SMEM_B_BYTES    (32 * 136 * 4)
#define SGEMM_SMEM      (SMEM_AS_BYTES + 2 * SMEM_B_BYTES)

__global__ __launch_bounds__(256, 2) void sgemm128_kernel(
    const float* __restrict__ A, const float* __restrict__ W,
    const float* __restrict__ av_src, const float* __restrict__ av_dst,
    __half* __restrict__ Ch, int M)
{
    extern __shared__ char dynsmem[];
    float    (*As)[36]  = reinterpret_cast<float(*)[36]>(dynsmem);
    uint32_t (*Bh)[136] = reinterpret_cast<uint32_t(*)[136]>(dynsmem + SMEM_AS_BYTES);
    uint32_t (*Bl)[136] = reinterpret_cast<uint32_t(*)[136]>(dynsmem + SMEM_AS_BYTES + SMEM_B_BYTES);

    int block_row = blockIdx.x * 128;
    int tid  = threadIdx.x;
    int lane = tid & 31;
    int warp = tid >> 5;
    int wr = warp >> 1;
    int wc = warp & 1;              // == attention head
    int lq = lane >> 2;
    int lr = lane & 3;

    float c[2][8][4];
#pragma unroll
    for (int mt = 0; mt < 2; mt++)
#pragma unroll
        for (int nt = 0; nt < 8; nt++)
#pragma unroll
            for (int i = 0; i < 4; i++) c[mt][nt][i] = 0.f;

    for (int kc = 0; kc < 4; kc++) {
        int k0 = kc * 32;
#pragma unroll
        for (int i = 0; i < 4; i++) {
            int idx = tid + i * 256;
            int ar = idx >> 3, ac4 = (idx & 7) * 4;
            int gr = block_row + ar;
            float4 v = make_float4(0.f, 0.f, 0.f, 0.f);
            if (gr < M) v = *reinterpret_cast<const float4*>(&A[(size_t)gr * 128 + k0 + ac4]);
            *reinterpret_cast<float4*>(&As[ar][ac4]) = v;
            // B: convert to tf32 hi/lo once, cooperatively
            int br = idx >> 5, bc4 = (idx & 31) * 4;
            float4 wv = *reinterpret_cast<const float4*>(&W[(size_t)(k0 + br) * 128 + bc4]);
            uint32_t h0 = f2tf32(wv.x), h1 = f2tf32(wv.y), h2 = f2tf32(wv.z), h3 = f2tf32(wv.w);
            uint32_t l0 = f2tf32(wv.x - __uint_as_float(h0));
            uint32_t l1 = f2tf32(wv.y - __uint_as_float(h1));
            uint32_t l2 = f2tf32(wv.z - __uint_as_float(h2));
            uint32_t l3 = f2tf32(wv.w - __uint_as_float(h3));
            *reinterpret_cast<uint4*>(&Bh[br][bc4]) = make_uint4(h0, h1, h2, h3);
            *reinterpret_cast<uint4*>(&Bl[br][bc4]) = make_uint4(l0, l1, l2, l3);
        }
        __syncthreads();
#pragma unroll
        for (int ks = 0; ks < 4; ks++) {
            int k = ks * 8;
            uint32_t ah[2][4], al[2][4];
#pragma unroll
            for (int mt = 0; mt < 2; mt++) {
                int r0 = wr * 32 + mt * 16 + lq;
                float x0 = As[r0][k + lr];
                float x1 = As[r0 + 8][k + lr];
                float x2 = As[r0][k + lr + 4];
                float x3 = As[r0 + 8][k + lr + 4];
                ah[mt][0] = f2tf32(x0); al[mt][0] = f2tf32(x0 - __uint_as_float(ah[mt][0]));
                ah[mt][1] = f2tf32(x1); al[mt][1] = f2tf32(x1 - __uint_as_float(ah[mt][1]));
                ah[mt][2] = f2tf32(x2); al[mt][2] = f2tf32(x2 - __uint_as_float(ah[mt][2]));
                ah[mt][3] = f2tf32(x3); al[mt][3] = f2tf32(x3 - __uint_as_float(ah[mt][3]));
            }
#pragma unroll
            for (int nt = 0; nt < 8; nt++) {
                int ncol = wc * 64 + nt * 8 + lq;
                uint32_t bh[2], bl[2];
                bh[0] = Bh[k + lr][ncol];
                bh[1] = Bh[k + lr + 4][ncol];
                bl[0] = Bl[k + lr][ncol];
                bl[1] = Bl[k + lr + 4][ncol];
#pragma unroll
                for (int mt = 0; mt < 2; mt++) {
                    mma_tf32(c[mt][nt], ah[mt], bh);
                    mma_tf32(c[mt][nt], ah[mt], bl);
                    mma_tf32(c[mt][nt], al[mt], bh);
                }
            }
        }
        __syncthreads();
    }

    // store C as fp16
#pragma unroll
    for (int mt = 0; mt < 2; mt++) {
        int r0 = block_row + wr * 32 + mt * 16 + lq;
#pragma unroll
        for (int nt = 0; nt < 8; nt++) {
            int cc = wc * 64 + nt * 8 + lr * 2;
            if (r0 < M)
                *reinterpret_cast<__half2*>(&Ch[(size_t)r0 * 128 + cc]) =
                    __floats2half2_rn(c[mt][nt][0], c[mt][nt][1]);
            if (r0 + 8 < M)
                *reinterpret_cast<__half2*>(&Ch[(size_t)(r0 + 8) * 128 + cc]) =
                    __floats2half2_rn(c[mt][nt][2], c[mt][nt][3]);
        }
    }

    // fused e_src / e_dst epilogue from fp32 accumulators
#pragma unroll
    for (int mt = 0; mt < 2; mt++) {
#pragma unroll
        for (int half = 0; half < 2; half++) {
            float ps = 0.f, pd = 0.f;
#pragma unroll
            for (int nt = 0; nt < 8; nt++) {
                int cc = wc * 64 + nt * 8 + lr * 2;
                float v0 = c[mt][nt][half * 2 + 0];
                float v1 = c[mt][nt][half * 2 + 1];
                ps += v0 * av_src[cc] + v1 * av_src[cc + 1];
                pd += v0 * av_dst[cc] + v1 * av_dst[cc + 1];
            }
            ps += __shfl_xor_sync(0xffffffffu, ps, 1);
            pd += __shfl_xor_sync(0xffffffffu, pd, 1);
            ps += __shfl_xor_sync(0xffffffffu, ps, 2);
            pd += __shfl_xor_sync(0xffffffffu, pd, 2);
            int row = block_row + wr * 32 + mt * 16 + lq + half * 8;
            if (lr == 0 && row < M) {
                g_es[2 * row + wc] = ps;
                g_ed[2 * row + wc] = pd;
            }
        }
    }
}

__device__ __forceinline__ float lrelu(float x) { return x > 0.f ? x : 0.2f * x; }

// ---------------- fused softmax-aggregate (round-13 form) ----------------
// Warp per dst node; 2 edges per step (lanes 0-15 edge k, 16-31 edge k+1;
// one uint4 = 8 cols per lane; merge halves with shfl_xor(16)).
// deg<=32 fast path: metadata loaded once, logits kept in registers.
__global__ __launch_bounds__(256) void agg_kernel(
    const __half* __restrict__ h, const float* __restrict__ bias,
    float* __restrict__ out, int n)
{
    int w = (blockIdx.x * blockDim.x + threadIdx.x) >> 5;
    int lane = threadIdx.x & 31;
    if (w >= n) return;
    int start = g_rowptr[w], end = g_rowptr[w + 1];
    int deg = end - start;
    const float2* es2 = reinterpret_cast<const float2*>(g_es);
    const float2* ed2 = reinterpret_cast<const float2*>(g_ed);
    float2 ed = ed2[w];

    const uint4* h16 = reinterpret_cast<const uint4*>(h);  // 16 uint4 per row
    int l15    = lane & 15;
    int halfid = lane >> 4;
    bool headA = (l15 < 8);

    float acc[8];
#pragma unroll
    for (int j = 0; j < 8; j++) acc[j] = 0.f;
    float den0 = 0.f, den1 = 0.f;

    if (deg <= 32) {
        // ---- fast path: one metadata load, logits in regs ----
        int s = 0; float l0 = -3.0e38f, l1 = -3.0e38f;
        if (lane < deg) {
            s = g_col[start + lane];
            float2 es = es2[s];
            l0 = lrelu(es.x + ed.x);
            l1 = lrelu(es.y + ed.y);
        }
        float m0 = l0, m1 = l1;
#pragma unroll
        for (int o = 16; o; o >>= 1) {
            m0 = fmaxf(m0, __shfl_xor_sync(0xffffffffu, m0, o));
            m1 = fmaxf(m1, __shfl_xor_sync(0xffffffffu, m1, o));
        }
        float w0 = 0.f, w1 = 0.f;
        if (lane < deg) { w0 = __expf(l0 - m0); w1 = __expf(l1 - m1); }
        den0 = w0; den1 = w1;
#pragma unroll 4
        for (int k2 = 0; k2 < deg; k2 += 2) {
            int e = k2 + halfid;
            int   ss = __shfl_sync(0xffffffffu, s,  e & 31);
            float wa = __shfl_sync(0xffffffffu, w0, e & 31);
            float wb = __shfl_sync(0xffffffffu, w1, e & 31);
            float wk = headA ? wa : wb;
            if (e >= deg) wk = 0.f;
            uint4 u = h16[(size_t)ss * 16 + l15];
            float2 f0 = __half22float2(*reinterpret_cast<const __half2*>(&u.x));
            float2 f1 = __half22float2(*reinterpret_cast<const __half2*>(&u.y));
            float2 f2 = __half22float2(*reinterpret_cast<const __half2*>(&u.z));
            float2 f3 = __half22float2(*reinterpret_cast<const __half2*>(&u.w));
            acc[0] += wk * f0.x; acc[1] += wk * f0.y;
            acc[2] += wk * f1.x; acc[3] += wk * f1.y;
            acc[4] += wk * f2.x; acc[5] += wk * f2.y;
            acc[6] += wk * f3.x; acc[7] += wk * f3.y;
        }
    } else {
        // ---- general path ----
        float m0 = -3.0e38f, m1 = -3.0e38f;
        for (int j = start + lane; j < end; j += 32) {
            int s = g_col[j];
            float2 es = es2[s];
            m0 = fmaxf(m0, lrelu(es.x + ed.x));
            m1 = fmaxf(m1, lrelu(es.y + ed.y));
        }
#pragma unroll
        for (int o = 16; o; o >>= 1) {
            m0 = fmaxf(m0, __shfl_xor_sync(0xffffffffu, m0, o));
            m1 = fmaxf(m1, __shfl_xor_sync(0xffffffffu, m1, o));
        }
        for (int chunk = start; chunk < end; chunk += 32) {
            int j = chunk + lane;
            int s = 0; float w0 = 0.f, w1 = 0.f;
            if (j < end) {
                s = g_col[j];
                float2 es = es2[s];
                w0 = __expf(lrelu(es.x + ed.x) - m0);
                w1 = __expf(lrelu(es.y + ed.y) - m1);
            }
            den0 += w0; den1 += w1;
            int cnt = min(32, end - chunk);
#pragma unroll 4
            for (int k2 = 0; k2 < cnt; k2 += 2) {
                int e = k2 + halfid;
                int   ss = __shfl_sync(0xffffffffu, s,  e & 31);
                float wa = __shfl_sync(0xffffffffu, w0, e & 31);
                float wb = __shfl_sync(0xffffffffu, w1, e & 31);
                float wk = headA ? wa : wb;
                if (e >= cnt) wk = 0.f;
                uint4 u = h16[(size_t)ss * 16 + l15];
                float2 f0 = __half22float2(*reinterpret_cast<const __half2*>(&u.x));
                float2 f1 = __half22float2(*reinterpret_cast<const __half2*>(&u.y));
                float2 f2 = __half22float2(*reinterpret_cast<const __half2*>(&u.z));
                float2 f3 = __half22float2(*reinterpret_cast<const __half2*>(&u.w));
                acc[0] += wk * f0.x; acc[1] += wk * f0.y;
                acc[2] += wk * f1.x; acc[3] += wk * f1.y;
                acc[4] += wk * f2.x; acc[5] += wk * f2.y;
                acc[6] += wk * f3.x; acc[7] += wk * f3.y;
            }
        }
    }

    // merge the two edge-subsets (lanes l and l+16 cover identical cols)
#pragma unroll
    for (int j = 0; j < 8; j++)
        acc[j] += __shfl_xor_sync(0xffffffffu, acc[j], 16);

#pragma unroll
    for (int o = 16; o; o >>= 1) {
        den0 += __shfl_xor_sync(0xffffffffu, den0, o);
        den1 += __shfl_xor_sync(0xffffffffu, den1, o);
    }
    float inv = 1.0f / (headA ? den0 : den1);

    // output: lane<16 writes float4 at col 8*l15, lane>=16 at 8*l15+4
    int fo = halfid * 4;
    float4 bb = reinterpret_cast<const float4*>(bias)[2 * l15 + halfid];
    float o0 = acc[fo + 0] * inv + bb.x;
    float o1 = acc[fo + 1] * inv + bb.y;
    float o2 = acc[fo + 2] * inv + bb.z;
    float o3 = acc[fo + 3] * inv + bb.w;
    o0 = o0 > 0.f ? o0 : expm1f(o0);
    o1 = o1 > 0.f ? o1 : expm1f(o1);
    o2 = o2 > 0.f ? o2 : expm1f(o2);
    o3 = o3 > 0.f ? o3 : expm1f(o3);
    reinterpret_cast<float4*>(out)[(size_t)w * 32 + 2 * l15 + halfid] =
        make_float4(o0, o1, o2, o3);
}

// ---------------- host ----------------
extern "C" void kernel_launch(void* const* d_in, const int* in_sizes, int n_in,
                              void* d_out, int out_size)
{
    const float* x   = (const float*)d_in[0];
    const int*   ei  = (const int*)d_in[1];
    const float* W1  = (const float*)d_in[2];
    const float* as1 = (const float*)d_in[3];
    const float* ad1 = (const float*)d_in[4];
    const float* b1  = (const float*)d_in[5];
    const float* W2  = (const float*)d_in[6];
    const float* as2 = (const float*)d_in[7];
    const float* ad2 = (const float*)d_in[8];
    const float* b2  = (const float*)d_in[9];
    const float* W3  = (const float*)d_in[10];
    const float* as3 = (const float*)d_in[11];
    const float* ad3 = (const float*)d_in[12];
    const float* b3  = (const float*)d_in[13];
    float*       out = (float*)d_out;

    int n = in_sizes[0] / FDIM;          // 50000
    int E = in_sizes[1] / 2;             // 800000

    void* pH; cudaGetSymbolAddress(&pH, g_h);
    void* pB; cudaGetSymbolAddress(&pB, g_bufB);
    __half* hbuf = (__half*)pH;
    float*  bufB = (float*)pB;

    static int smem_set = 0;
    if (!smem_set) {
        cudaFuncSetAttribute(sgemm128_kernel,
                             cudaFuncAttributeMaxDynamicSharedMemorySize, SGEMM_SMEM);
        smem_set = 1;
    }

    int nblkNodes = (n + 255) / 256;
    int nblkEdges = (E + n + 255) / 256;
    int nblkWarp  = (n * 32 + 255) / 256;
    int nblkGemm  = (n + 127) / 128;

    // launches 0..2: CSR front half
    zero_counts_kernel<<<nblkNodes, 256>>>(n);
    hist_kernel<<<nblkEdges, 256>>>(ei, E, n);
    scan_kernel<<<1, 1024>>>(n);
    // launch 3: sgemm1 (ncu capture offset)
    sgemm128_kernel<<<nblkGemm, 256, SGEMM_SMEM>>>(x, W1, as1, ad1, hbuf, n);
    // launch 4: scatter completes CSR before agg1
    scatter_kernel<<<nblkEdges, 256>>>(ei, E, n);
    // launch 5: agg1
    agg_kernel<<<nblkWarp, 256>>>(hbuf, b1, bufB, n);
    // layer 2
    sgemm128_kernel<<<nblkGemm, 256, SGEMM_SMEM>>>(bufB, W2, as2, ad2, hbuf, n);
    agg_kernel<<<nblkWarp, 256>>>(hbuf, b2, bufB, n);
    // layer 3
    sgemm128_kernel<<<nblkGemm, 256, SGEMM_SMEM>>>(bufB, W3, as3, ad3, hbuf, n);
    agg_kernel<<<nblkWarp, 256>>>(hbuf, b3, out, n);
}